// round 11
// baseline (speedup 1.0000x reference)
#include <cuda_runtime.h>

#define NEG_PENALTY 0.03f
#define BATCH 64
#define NCLS  2048
#define LL    1024
#define NT    1024
#define GRID  BATCH
#define NB    1024
#define FULLM 0xffffffffu
#define BMIN   (-6.5f)
#define BSCALE (1024.0f / 13.0f)   // buckets cover [-6.5, 6.5]; clamp handles tails

__device__ float    g_accum  = 0.0f;
__device__ unsigned g_ticket = 0;    // self-resetting via atomicInc wrap

__device__ __forceinline__ int bucket_of(float v) {
    int bkt = (int)((v - BMIN) * BSCALE);
    return min(max(bkt, 0), NB - 1);
}

__global__ __launch_bounds__(NT)
void ranking_loss_kernel(const float* __restrict__ ranks,
                         const int*   __restrict__ labels,
                         const void*  __restrict__ ids_raw,
                         float* __restrict__ out)
{
    __shared__ float s_rank[NCLS];     // staged ranks row (coalesced)
    __shared__ char  s_lab8[NCLS];     // staged labels row (1 byte each)
    __shared__ int   s_bcnt[NB];       // per-bucket pos count
    __shared__ int   s_boff[NB + 1];   // exclusive offsets (counting sort)
    __shared__ float s_sorted[LL];     // value-sorted pos (zeros beyond np)
    __shared__ float s_pre[LL];        // inclusive prefix sums of s_sorted
    __shared__ int   s_iscan[32];
    __shared__ float s_fscan[32];
    __shared__ float s_warp[32];

    const int b    = blockIdx.x;       // one CTA per batch
    const int tid  = threadIdx.x;
    const int lane = tid & 31;
    const int wid  = tid >> 5;

    // --- dtype sniff: int64 ids have zero high words at odd 32-bit indices ---
    const int* w32 = (const int*)ids_raw;
    const bool is64 = ((w32[201] | w32[401] | w32[601] | w32[801]) == 0);
    const long long* w64 = (const long long*)ids_raw;

    // ---- all-independent loads (MLP=5): id + coalesced row staging ----
    int   id  = is64 ? (int)w64[tid] : w32[tid];
    const float* rrow = ranks  + b * NCLS;
    const int*   lrow = labels + b * NCLS;
    float rv0 = rrow[tid];
    float rv1 = rrow[tid + LL];
    int   lv0 = lrow[tid];
    int   lv1 = lrow[tid + LL];

    s_bcnt[tid]      = 0;
    s_sorted[tid]    = 0.0f;
    s_rank[tid]      = rv0;
    s_rank[tid + LL] = rv1;
    s_lab8[tid]      = (char)lv0;
    s_lab8[tid + LL] = (char)lv1;
    __syncthreads();                                  // B0 (staging + zero)

    // ---- smem gather ----
    const float r     = s_rank[id];
    const bool  ispos = (s_lab8[id] == 1);
    const float x     = r + NEG_PENALTY;              // used if neg
    const int   bkt   = bucket_of(ispos ? r : x);     // monotone map

    int sidx = 0;
    if (ispos) sidx = atomicAdd(&s_bcnt[bkt], 1);
    __syncthreads();                                  // B1

    // ---- block scan of bucket counts -> exclusive offsets ----
    int v = s_bcnt[tid];
    int inc = v;
    #pragma unroll
    for (int d = 1; d < 32; d <<= 1) {
        int t = __shfl_up_sync(FULLM, inc, d);
        if (lane >= d) inc += t;
    }
    if (lane == 31) s_iscan[wid] = inc;
    __syncthreads();                                  // B2
    if (wid == 0) {
        int wv = s_iscan[lane];
        int winc = wv;
        #pragma unroll
        for (int d = 1; d < 32; d <<= 1) {
            int t = __shfl_up_sync(FULLM, winc, d);
            if (lane >= d) winc += t;
        }
        s_iscan[lane] = winc;
    }
    __syncthreads();                                  // B3
    int excl = ((wid > 0) ? s_iscan[wid - 1] : 0) + inc - v;
    s_boff[tid] = excl;
    if (tid == NT - 1) s_boff[NB] = excl + v;         // = np
    __syncthreads();                                  // B4

    // ---- counting-sort scatter of pos values ----
    if (ispos) s_sorted[s_boff[bkt] + sidx] = r;
    __syncthreads();                                  // B5

    // ---- block scan of sorted values -> inclusive prefix sums ----
    float fv = s_sorted[tid];
    float finc = fv;
    #pragma unroll
    for (int d = 1; d < 32; d <<= 1) {
        float t = __shfl_up_sync(FULLM, finc, d);
        if (lane >= d) finc += t;
    }
    if (lane == 31) s_fscan[wid] = finc;
    __syncthreads();                                  // B6
    if (wid == 0) {
        float wv = s_fscan[lane];
        float winc = wv;
        #pragma unroll
        for (int d = 1; d < 32; d <<= 1) {
            float t = __shfl_up_sync(FULLM, winc, d);
            if (lane >= d) winc += t;
        }
        s_fscan[lane] = winc;
    }
    __syncthreads();                                  // B7
    s_pre[tid] = ((wid > 0) ? s_fscan[wid - 1] : 0.0f) + finc;
    __syncthreads();                                  // B8

    // ---- per-neg closed form: (k0+c)*x - (S0+s) ----
    float acc = 0.0f;
    if (!ispos) {
        int k0 = s_boff[bkt];          // pos strictly in lower buckets (< x)
        int e  = s_boff[bkt + 1];
        int c = 0; float s = 0.0f;
        for (int i = k0; i < e; i++) { // partial bucket, ~0-3 elems
            float p = s_sorted[i];
            if (p < x) { c++; s += p; }
        }
        float S0 = (k0 > 0) ? s_pre[k0 - 1] : 0.0f;
        acc = (float)(k0 + c) * x - (S0 + s);
    }

    // ---- block reduce (32 warps) + scalar-accumulator tail ----
    #pragma unroll
    for (int d = 16; d >= 1; d >>= 1)
        acc += __shfl_down_sync(FULLM, acc, d);
    if (lane == 0) s_warp[wid] = acc;
    __syncthreads();                                  // B9
    if (wid == 0 && lane == 0) {
        float a2 = 0.0f;
        #pragma unroll
        for (int k = 0; k < 32; k++) a2 += s_warp[k];
        atomicAdd(&g_accum, a2);
        __threadfence();
        unsigned t = atomicInc(&g_ticket, GRID - 1);  // wraps at 63
        if (t == GRID - 1) {                          // last CTA finishes up
            float total = atomicAdd(&g_accum, 0.0f);  // atomic read
            out[0] = total * (1.0f / (float)BATCH);
            g_accum = 0.0f;                           // reset for next call
            __threadfence();
        }
    }
}

extern "C" void kernel_launch(void* const* d_in, const int* in_sizes, int n_in,
                              void* d_out, int out_size)
{
    const float* ranks  = (const float*)d_in[0];   // [B, C] f32
    const int*   labels = (const int*)d_in[1];     // [B, C] i32
    const void*  ids    = d_in[2];                 // [L] i64 or i32 (sniffed)
    float* out = (float*)d_out;                    // [1] f32

    ranking_loss_kernel<<<GRID, NT>>>(ranks, labels, ids, out);
}